// round 1
// baseline (speedup 1.0000x reference)
#include <cuda_runtime.h>
#include <math.h>

#define B_ 2
#define C_ 64
#define S_ 128
#define SS_ 16384      /* S*S */
#define NPIX_ 32768    /* B*S*S */

// ---------------- scratch (static __device__, no allocations) ----------------
__device__ float  g_q  [B_*C_*SS_];
__device__ float  g_k  [B_*C_*SS_];
__device__ float  g_v  [B_*C_*SS_];
__device__ float  g_out[B_*C_*SS_];
__device__ float2 g_Tf [B_*SS_];        // forward DFT row-stage temp
__device__ float2 g_X  [B_*SS_];        // ortho fft2 of out[:,32]
__device__ float2 g_Y  [B_*C_*SS_];     // X * wsum
__device__ float2 g_G  [B_*C_*SS_];     // inverse stage-1 (u dir)
__device__ float2 g_T2 [B_*C_*SS_];     // inverse stage-2 (u dir done)
__device__ float  g_out1[B_*C_*SS_];
__device__ float  g_Mt [C_*C_];         // combined conv chain, transposed [cin][o]
__device__ float  g_bias2[C_];
__device__ float  g_Cf[SS_];            // cos(2*pi*u*h/128)
__device__ float  g_Sf[SS_];            // sin(2*pi*u*h/128)
__device__ float2 g_E16[256];           // e^{+2pi i a b/16}  [a*16+b]
__device__ float2 g_E8 [64];            // e^{+2pi i a b/8}   [a*8+b]
__device__ float2 g_TW [128];           // e^{+2pi i h2 u1/128} [h2*8+u1]
__device__ float  g_part[128];

__device__ __forceinline__ float2 cmul(float2 a, float2 b) {
    return make_float2(a.x*b.x - a.y*b.y, a.x*b.y + a.y*b.x);
}

// ---------------- trig tables (recomputed deterministically each call) ------
__global__ void init_tables_kernel() {
    int t = blockIdx.x * blockDim.x + threadIdx.x;   // 0..16383
    if (t < SS_) {
        int u = t >> 7, h = t & 127;
        double a = (double)(u * h) / 64.0;           // angle/pi
        double s, c; sincospi(a, &s, &c);
        g_Cf[t] = (float)c; g_Sf[t] = (float)s;
    }
    if (t < 256) {
        int a = t >> 4, b = t & 15;
        double s, c; sincospi((double)(a*b) / 8.0, &s, &c);
        g_E16[t] = make_float2((float)c, (float)s);
    }
    if (t < 64) {
        int a = t >> 3, b = t & 7;
        double s, c; sincospi((double)(a*b) / 4.0, &s, &c);
        g_E8[t] = make_float2((float)c, (float)s);
    }
    if (t < 128) {
        int h2 = t >> 3, u1 = t & 7;
        double s, c; sincospi((double)(h2*u1) / 64.0, &s, &c);
        g_TW[t] = make_float2((float)c, (float)s);
    }
}

// ---------------- q/k/v 1x1 convs ------------------------------------------
__global__ void qkv_kernel(const float* __restrict__ fs,
                           const float* __restrict__ wq,
                           const float* __restrict__ wk,
                           const float* __restrict__ wv) {
    __shared__ float Wt[C_*C_];   // transposed: Wt[cin*64+o]
    const float* w; float* outp;
    if (blockIdx.y == 0)      { w = wq; outp = g_q; }
    else if (blockIdx.y == 1) { w = wk; outp = g_k; }
    else                      { w = wv; outp = g_v; }
    for (int i = threadIdx.x; i < C_*C_; i += blockDim.x) {
        int cin = i >> 6, o = i & 63;
        Wt[(cin << 6) + o] = w[(o << 6) + cin];
    }
    __syncthreads();
    int p  = blockIdx.x * blockDim.x + threadIdx.x;   // pixel 0..32767
    int b  = p >> 14, sp = p & 16383;
    int base = (b << 6) << 14;
    float acc[64];
#pragma unroll
    for (int o = 0; o < 64; o++) acc[o] = 0.f;
    const float4* Wt4 = (const float4*)Wt;
    for (int cin = 0; cin < 64; cin++) {
        float x = fs[base + (cin << 14) + sp];
#pragma unroll
        for (int o4 = 0; o4 < 16; o4++) {
            float4 w4 = Wt4[(cin << 4) + o4];
            acc[o4*4+0] += x * w4.x;
            acc[o4*4+1] += x * w4.y;
            acc[o4*4+2] += x * w4.z;
            acc[o4*4+3] += x * w4.w;
        }
    }
#pragma unroll
    for (int o = 0; o < 64; o++) outp[base + (o << 14) + sp] = acc[o];
}

// ---------------- 3x3 local softmax attention ------------------------------
__global__ void att_kernel(const float* __restrict__ relh,
                           const float* __restrict__ relw) {
    __shared__ float kt[18*18];
    __shared__ float vt[18*18];
    int bc   = blockIdx.y;                 // b*64 + c
    int c    = bc & 63;
    int tile = blockIdx.x;
    int th0  = (tile >> 3) << 4, tw0 = (tile & 7) << 4;
    int tid  = threadIdx.x;
    int base = bc << 14;
    for (int i = tid; i < 324; i += 256) {
        int r = i / 18, q = i % 18;
        int gh = th0 - 1 + r, gw = tw0 - 1 + q;
        bool in = ((unsigned)gh < 128u) && ((unsigned)gw < 128u);
        int gi = base + (gh << 7) + gw;
        kt[i] = in ? g_k[gi] : 0.f;
        vt[i] = in ? g_v[gi] : 0.f;
    }
    __syncthreads();
    int ty = tid >> 4, tx = tid & 15;
    int h = th0 + ty, w = tw0 + tx;
    float qv = g_q[base + (h << 7) + w];
    bool isH = c < 32;
    float b0, b1, b2;
    if (isH) { b0 = relh[c*3]; b1 = relh[c*3+1]; b2 = relh[c*3+2]; }
    else     { int cc = c - 32; b0 = relw[cc*3]; b1 = relw[cc*3+1]; b2 = relw[cc*3+2]; }
    float l[9], vv[9];
#pragma unroll
    for (int ki = 0; ki < 3; ki++) {
        float bh = (ki == 0) ? b0 : (ki == 1) ? b1 : b2;
#pragma unroll
        for (int kj = 0; kj < 3; kj++) {
            float bw = (kj == 0) ? b0 : (kj == 1) ? b1 : b2;
            float bias = isH ? bh : bw;
            float kvv = kt[(ty+ki)*18 + tx + kj];
            l[ki*3+kj]  = qv * (kvv + bias);
            vv[ki*3+kj] = vt[(ty+ki)*18 + tx + kj];
        }
    }
    float m = l[0];
#pragma unroll
    for (int i = 1; i < 9; i++) m = fmaxf(m, l[i]);
    float s = 0.f, o = 0.f;
#pragma unroll
    for (int i = 0; i < 9; i++) {
        float e = __expf(l[i] - m);
        s += e; o += e * vv[i];
    }
    g_out[base + (h << 7) + w] = o / s;
}

// ---------------- forward ortho fft2 of out[:,32] (direct DFT, tiny) -------
__global__ void f1_kernel() {        // transform along h, e^{-i}
    int bu = blockIdx.x;             // b*128+u
    int b = bu >> 7, u = bu & 127;
    int w = threadIdx.x;
    const float* x = g_out + (((b << 6) + 32) << 14);
    float ar = 0.f, ai = 0.f;
    for (int h = 0; h < 128; h++) {
        float xv = x[(h << 7) + w];
        float cz = g_Cf[(u << 7) + h], sz = g_Sf[(u << 7) + h];
        ar += xv * cz; ai -= xv * sz;
    }
    g_Tf[(bu << 7) + w] = make_float2(ar, ai);
}

__global__ void f2_kernel() {        // transform along w, e^{-i}, scale 1/128
    __shared__ float2 row[128];
    int bu = blockIdx.x;
    int v = threadIdx.x;
    row[v] = g_Tf[(bu << 7) + v];
    __syncthreads();
    float ar = 0.f, ai = 0.f;
    for (int w = 0; w < 128; w++) {
        float2 t = row[w];
        float cz = g_Cf[(v << 7) + w], sz = g_Sf[(v << 7) + w];
        ar += t.x * cz + t.y * sz;
        ai += t.y * cz - t.x * sz;
    }
    g_X[(bu << 7) + v] = make_float2(ar * (1.f/128.f), ai * (1.f/128.f));
}

// ---------------- weight reduce (537MB read, the HBM-bound kernel) + X mult -
__global__ void wred_kernel(const float* __restrict__ wrp,
                            const float* __restrict__ wip) {
    int t = blockIdx.x * blockDim.x + threadIdx.x;   // 0..262143
    int cin = t >> 12;
    int q4  = t & 4095;
    const float4* R = (const float4*)wrp;
    const float4* I = (const float4*)wip;
    float4 sr = make_float4(0.f,0.f,0.f,0.f);
    float4 si = make_float4(0.f,0.f,0.f,0.f);
#pragma unroll 8
    for (int o = 0; o < 64; o++) {
        float4 a = __ldg(&R[(((cin << 6) + o) << 12) + q4]);
        float4 b = __ldg(&I[(((cin << 6) + o) << 12) + q4]);
        sr.x += a.x; sr.y += a.y; sr.z += a.z; sr.w += a.w;
        si.x += b.x; si.y += b.y; si.z += b.z; si.w += b.w;
    }
    float wr[4] = { sr.x, sr.y, sr.z, sr.w };
    float wi[4] = { si.x, si.y, si.z, si.w };
#pragma unroll
    for (int b = 0; b < 2; b++) {
#pragma unroll
        for (int k = 0; k < 4; k++) {
            float2 X = g_X[(b << 14) + (q4 << 2) + k];
            float2 y;
            y.x = X.x * wr[k] - X.y * wi[k];
            y.y = X.x * wi[k] + X.y * wr[k];
            g_Y[(((b << 6) + cin) << 14) + (q4 << 2) + k] = y;
        }
    }
}

// ---------------- inverse 2D transform, mixed radix 8x16 --------------------
// stage 1 along u: G[u1,h2] = tw(h2,u1) * sum_{u2} E16[h2,u2] Y[u1+8u2]
__global__ void s1_kernel() {
    __shared__ float2 E16s[256];
    __shared__ float2 TWs[128];
    int tid = threadIdx.x;
    for (int i = tid; i < 256; i += 128) E16s[i] = g_E16[i];
    if (tid < 128) TWs[tid] = g_TW[tid];
    __syncthreads();
    int img = blockIdx.x;     // 0..127 (b*64+cin)
    int u1  = blockIdx.y;     // 0..7
    int v   = tid;
    int base = img << 14;
    float2 acc[16];
#pragma unroll
    for (int h2 = 0; h2 < 16; h2++) acc[h2] = make_float2(0.f, 0.f);
    for (int u2 = 0; u2 < 16; u2++) {
        float2 y = g_Y[base + ((u1 + (u2 << 3)) << 7) + v];
#pragma unroll
        for (int h2 = 0; h2 < 16; h2++) {
            float2 e = E16s[(h2 << 4) + u2];
            acc[h2].x += e.x * y.x - e.y * y.y;
            acc[h2].y += e.x * y.y + e.y * y.x;
        }
    }
#pragma unroll
    for (int h2 = 0; h2 < 16; h2++) {
        float2 g = cmul(TWs[(h2 << 3) + u1], acc[h2]);
        g_G[base + (((u1 << 4) + h2) << 7) + v] = g;
    }
}

// stage 2 along u: T[h2+16h1] = sum_{u1} E8[h1,u1] G[u1,h2]
__global__ void s2_kernel() {
    __shared__ float2 E8s[64];
    int tid = threadIdx.x;
    if (tid < 64) E8s[tid] = g_E8[tid];
    __syncthreads();
    int img = blockIdx.x;
    int h2  = blockIdx.y;     // 0..15
    int v   = tid;
    int base = img << 14;
    float2 acc[8];
#pragma unroll
    for (int h1 = 0; h1 < 8; h1++) acc[h1] = make_float2(0.f, 0.f);
    for (int u1 = 0; u1 < 8; u1++) {
        float2 g = g_G[base + (((u1 << 4) + h2) << 7) + v];
#pragma unroll
        for (int h1 = 0; h1 < 8; h1++) {
            float2 e = E8s[(h1 << 3) + u1];
            acc[h1].x += e.x * g.x - e.y * g.y;
            acc[h1].y += e.x * g.y + e.y * g.x;
        }
    }
#pragma unroll
    for (int h1 = 0; h1 < 8; h1++) {
        int h = h2 + (h1 << 4);
        g_T2[base + (h << 7) + v] = acc[h1];
    }
}

// stages 3+4 along w, fused per-row; emits real part * (1/128)
__global__ void s34_kernel() {
    __shared__ float2 rowT[128];
    __shared__ float2 rowH[128];
    __shared__ float2 E16s[256];
    __shared__ float2 E8s[64];
    __shared__ float2 TWs[128];
    int tid = threadIdx.x;
    int rb  = blockIdx.x;      // img*128 + h
    for (int i = tid; i < 256; i += 128) E16s[i] = g_E16[i];
    if (tid < 64) E8s[tid] = g_E8[tid];
    TWs[tid]  = g_TW[tid];
    rowT[tid] = g_T2[(rb << 7) + tid];
    __syncthreads();
    {
        int v1 = tid >> 4, w2 = tid & 15;
        float2 acc = make_float2(0.f, 0.f);
#pragma unroll
        for (int v2 = 0; v2 < 16; v2++) {
            float2 e = E16s[(w2 << 4) + v2];
            float2 t = rowT[v1 + (v2 << 3)];
            acc.x += e.x * t.x - e.y * t.y;
            acc.y += e.x * t.y + e.y * t.x;
        }
        rowH[(v1 << 4) + w2] = cmul(TWs[(w2 << 3) + v1], acc);
    }
    __syncthreads();
    {
        int w2 = tid & 15, w1 = tid >> 4;   // w = w2 + 16*w1 == tid
        float r = 0.f;
#pragma unroll
        for (int v1 = 0; v1 < 8; v1++) {
            float2 e = E8s[(w1 << 3) + v1];
            float2 hh = rowH[(v1 << 4) + w2];
            r += e.x * hh.x - e.y * hh.y;
        }
        g_out1[(rb << 7) + tid] = r * (1.f/128.f);
    }
}

// ---------------- fold conv chain into one matrix + bias --------------------
__global__ void combine_kernel(const float* __restrict__ w0w,
                               const float* __restrict__ w0b,
                               const float* __restrict__ cvw,
                               const float* __restrict__ cvb,
                               const float* __restrict__ cv1w,
                               const float* __restrict__ cv1b) {
    __shared__ float sA[4096];
    __shared__ float sb1[64];
    int tid = threadIdx.x;
    for (int i = tid; i < 4096; i += 256) {
        int o = i >> 6, c = i & 63;
        float s = 0.f;
        for (int k = 0; k < 64; k++) s += w0w[(o << 6) + k] * cvw[(k << 6) + c];
        sA[i] = s;
    }
    if (tid < 64) {
        float s = 0.f;
        for (int k = 0; k < 64; k++) s += w0w[(tid << 6) + k] * cvb[k];
        sb1[tid] = s + w0b[tid];
    }
    __syncthreads();
    for (int i = tid; i < 4096; i += 256) {
        int o = i >> 6, c = i & 63;
        float s = 0.f;
        for (int k = 0; k < 64; k++) s += cv1w[(o << 6) + k] * sA[(k << 6) + c];
        g_Mt[(c << 6) + o] = s;   // transposed store
    }
    if (tid < 64) {
        float s = 0.f;
        for (int k = 0; k < 64; k++) s += cv1w[(tid << 6) + k] * sb1[k];
        g_bias2[tid] = s + cv1b[tid];
    }
}

// ---------------- fused out2 + mix + squared-error block partials -----------
__global__ void final_kernel(const float* __restrict__ ft,
                             const float* __restrict__ rate1,
                             const float* __restrict__ rate2) {
    __shared__ float Mt[C_*C_];
    __shared__ float bsh[64];
    __shared__ float red[256];
    int tid = threadIdx.x;
    for (int i = tid; i < C_*C_; i += 256) Mt[i] = g_Mt[i];
    if (tid < 64) bsh[tid] = g_bias2[tid];
    __syncthreads();
    int p = blockIdx.x * 256 + tid;   // pixel
    int b = p >> 14, sp = p & 16383;
    int base = (b << 6) << 14;
    float acc2[64];
#pragma unroll
    for (int o = 0; o < 64; o++) acc2[o] = 0.f;
    const float4* Mt4 = (const float4*)Mt;
    for (int cin = 0; cin < 64; cin++) {
        float x = g_out[base + (cin << 14) + sp];
#pragma unroll
        for (int o4 = 0; o4 < 16; o4++) {
            float4 w4 = Mt4[(cin << 4) + o4];
            acc2[o4*4+0] += x * w4.x;
            acc2[o4*4+1] += x * w4.y;
            acc2[o4*4+2] += x * w4.z;
            acc2[o4*4+3] += x * w4.w;
        }
    }
    float r1 = rate1[0], r2 = rate2[0];
    float ssum = 0.f;
    const float4* ftp = (const float4*)(ft + ((size_t)p << 6));
#pragma unroll
    for (int c4 = 0; c4 < 16; c4++) {
        float4 f = __ldg(&ftp[c4]);
        float fv[4] = { f.x, f.y, f.z, f.w };
#pragma unroll
        for (int j = 0; j < 4; j++) {
            int c = c4*4 + j;
            float o1 = g_out1[base + (c << 14) + sp];
            float mk = r1 * o1 + r2 * (acc2[c] + bsh[c]);
            float d = mk - fv[j];
            ssum += d * d;
        }
    }
    red[tid] = ssum;
    __syncthreads();
    for (int s = 128; s > 0; s >>= 1) {
        if (tid < s) red[tid] += red[tid + s];
        __syncthreads();
    }
    if (tid == 0) g_part[blockIdx.x] = red[0];
}

__global__ void reduce2_kernel(float* __restrict__ out) {
    __shared__ double red[128];
    int tid = threadIdx.x;
    red[tid] = (double)g_part[tid];
    __syncthreads();
    for (int s = 64; s > 0; s >>= 1) {
        if (tid < s) red[tid] += red[tid + s];
        __syncthreads();
    }
    if (tid == 0) out[0] = (float)(red[0] / 2097152.0);
}

// ---------------- launch ----------------------------------------------------
extern "C" void kernel_launch(void* const* d_in, const int* in_sizes, int n_in,
                              void* d_out, int out_size) {
    const float* fs    = (const float*)d_in[0];
    const float* ft    = (const float*)d_in[1];
    const float* wq    = (const float*)d_in[2];
    const float* wk    = (const float*)d_in[3];
    const float* wv    = (const float*)d_in[4];
    const float* relh  = (const float*)d_in[5];
    const float* relw  = (const float*)d_in[6];
    const float* w1r   = (const float*)d_in[7];
    const float* w1i   = (const float*)d_in[8];
    const float* w0w   = (const float*)d_in[9];
    const float* w0b   = (const float*)d_in[10];
    const float* cvw   = (const float*)d_in[11];
    const float* cvb   = (const float*)d_in[12];
    const float* cv1w  = (const float*)d_in[13];
    const float* cv1b  = (const float*)d_in[14];
    const float* rate1 = (const float*)d_in[15];
    const float* rate2 = (const float*)d_in[16];
    float* out = (float*)d_out;

    init_tables_kernel<<<64, 256>>>();
    qkv_kernel<<<dim3(128, 3), 256>>>(fs, wq, wk, wv);
    att_kernel<<<dim3(64, 128), 256>>>(relh, relw);
    f1_kernel<<<256, 128>>>();
    f2_kernel<<<256, 128>>>();
    wred_kernel<<<1024, 256>>>(w1r, w1i);
    s1_kernel<<<dim3(128, 8), 128>>>();
    s2_kernel<<<dim3(128, 16), 128>>>();
    s34_kernel<<<16384, 128>>>();
    combine_kernel<<<1, 256>>>(w0w, w0b, cvw, cvb, cv1w, cv1b);
    final_kernel<<<128, 256>>>(ft, rate1, rate2);
    reduce2_kernel<<<1, 128>>>(out);
}

// round 17
// speedup vs baseline: 1.2308x; 1.2308x over previous
#include <cuda_runtime.h>
#include <math.h>

#define B_ 2
#define C_ 64
#define S_ 128
#define SS_ 16384      /* S*S */

// ---------------- scratch (static __device__, no allocations) ----------------
__device__ float  g_q  [B_*C_*SS_];
__device__ float  g_k  [B_*C_*SS_];
__device__ float  g_v  [B_*C_*SS_];
__device__ float  g_out[B_*C_*SS_];
__device__ float2 g_X  [B_*SS_];        // ortho fft2 of out[:,32]
__device__ float2 g_W  [C_*SS_];        // wsum = sum_o (wr + i wi)
__device__ float  g_out1[B_*C_*SS_];
__device__ float  g_Mt [C_*C_];         // combined conv chain, transposed [cin][o]
__device__ float  g_bias2[C_];
__device__ float  g_Cf[SS_];            // cos(2*pi*u*h/128)
__device__ float  g_Sf[SS_];            // sin(2*pi*u*h/128)
__device__ float2 g_E16[256];           // e^{+2pi i a b/16}  [a*16+b]
__device__ float2 g_E8 [64];            // e^{+2pi i a b/8}   [a*8+b]
__device__ float2 g_TW [128];           // e^{+2pi i h2 u1/128} [h2*8+u1]
__device__ float  g_part[256];

__device__ __forceinline__ float2 cmul(float2 a, float2 b) {
    return make_float2(a.x*b.x - a.y*b.y, a.x*b.y + a.y*b.x);
}

// ---------------- trig tables ------------------------------------------------
__global__ void init_tables_kernel() {
    int t = blockIdx.x * blockDim.x + threadIdx.x;   // 0..16383
    if (t < SS_) {
        int u = t >> 7, h = t & 127;
        double a = (double)(u * h) / 64.0;           // angle/pi
        double s, c; sincospi(a, &s, &c);
        g_Cf[t] = (float)c; g_Sf[t] = (float)s;
    }
    if (t < 256) {
        int a = t >> 4, b = t & 15;
        double s, c; sincospi((double)(a*b) / 8.0, &s, &c);
        g_E16[t] = make_float2((float)c, (float)s);
    }
    if (t < 64) {
        int a = t >> 3, b = t & 7;
        double s, c; sincospi((double)(a*b) / 4.0, &s, &c);
        g_E8[t] = make_float2((float)c, (float)s);
    }
    if (t < 128) {
        int h2 = t >> 3, u1 = t & 7;
        double s, c; sincospi((double)(h2*u1) / 64.0, &s, &c);
        g_TW[t] = make_float2((float)c, (float)s);
    }
}

// ---------------- q/k/v 1x1 convs (split: 3 weights x 2 o-halves) -----------
__global__ void qkv_kernel(const float* __restrict__ fs,
                           const float* __restrict__ wq,
                           const float* __restrict__ wk,
                           const float* __restrict__ wv) {
    __shared__ float Wt[C_*32];   // transposed half: Wt[cin*32+o']
    int kind  = blockIdx.y >> 1;
    int halfo = blockIdx.y & 1;
    const float* w; float* outp;
    if (kind == 0)      { w = wq; outp = g_q; }
    else if (kind == 1) { w = wk; outp = g_k; }
    else                { w = wv; outp = g_v; }
    for (int i = threadIdx.x; i < C_*32; i += blockDim.x) {
        int cin = i >> 5, o = i & 31;
        Wt[i] = w[(((halfo << 5) + o) << 6) + cin];
    }
    __syncthreads();
    int p  = blockIdx.x * blockDim.x + threadIdx.x;   // pixel 0..32767
    int b  = p >> 14, sp = p & 16383;
    int base = (b << 6) << 14;
    float acc[32];
#pragma unroll
    for (int o = 0; o < 32; o++) acc[o] = 0.f;
    const float4* Wt4 = (const float4*)Wt;
    for (int cin = 0; cin < 64; cin++) {
        float x = fs[base + (cin << 14) + sp];
#pragma unroll
        for (int o4 = 0; o4 < 8; o4++) {
            float4 w4 = Wt4[(cin << 3) + o4];
            acc[o4*4+0] += x * w4.x;
            acc[o4*4+1] += x * w4.y;
            acc[o4*4+2] += x * w4.z;
            acc[o4*4+3] += x * w4.w;
        }
    }
#pragma unroll
    for (int o = 0; o < 32; o++)
        outp[base + (((halfo << 5) + o) << 14) + sp] = acc[o];
}

// ---------------- 3x3 local softmax attention ------------------------------
__global__ void att_kernel(const float* __restrict__ relh,
                           const float* __restrict__ relw) {
    __shared__ float kt[18*18];
    __shared__ float vt[18*18];
    int bc   = blockIdx.y;                 // b*64 + c
    int c    = bc & 63;
    int tile = blockIdx.x;
    int th0  = (tile >> 3) << 4, tw0 = (tile & 7) << 4;
    int tid  = threadIdx.x;
    int base = bc << 14;
    for (int i = tid; i < 324; i += 256) {
        int r = i / 18, q = i % 18;
        int gh = th0 - 1 + r, gw = tw0 - 1 + q;
        bool in = ((unsigned)gh < 128u) && ((unsigned)gw < 128u);
        int gi = base + (gh << 7) + gw;
        kt[i] = in ? g_k[gi] : 0.f;
        vt[i] = in ? g_v[gi] : 0.f;
    }
    __syncthreads();
    int ty = tid >> 4, tx = tid & 15;
    int h = th0 + ty, w = tw0 + tx;
    float qv = g_q[base + (h << 7) + w];
    bool isH = c < 32;
    float b0, b1, b2;
    if (isH) { b0 = relh[c*3]; b1 = relh[c*3+1]; b2 = relh[c*3+2]; }
    else     { int cc = c - 32; b0 = relw[cc*3]; b1 = relw[cc*3+1]; b2 = relw[cc*3+2]; }
    float l[9], vv[9];
#pragma unroll
    for (int ki = 0; ki < 3; ki++) {
        float bh = (ki == 0) ? b0 : (ki == 1) ? b1 : b2;
#pragma unroll
        for (int kj = 0; kj < 3; kj++) {
            float bw = (kj == 0) ? b0 : (kj == 1) ? b1 : b2;
            float bias = isH ? bh : bw;
            float kvv = kt[(ty+ki)*18 + tx + kj];
            l[ki*3+kj]  = qv * (kvv + bias);
            vv[ki*3+kj] = vt[(ty+ki)*18 + tx + kj];
        }
    }
    float m = l[0];
#pragma unroll
    for (int i = 1; i < 9; i++) m = fmaxf(m, l[i]);
    float s = 0.f, o = 0.f;
#pragma unroll
    for (int i = 0; i < 9; i++) {
        float e = __expf(l[i] - m);
        s += e; o += e * vv[i];
    }
    g_out[base + (h << 7) + w] = o / s;
}

// ---------------- fused forward fft2 of out[:,32] ---------------------------
// One block per (b, u0): phase A computes T[u0..u0+15][w] (h-transform) into
// smem; phase B transforms along w and writes X. Identical arithmetic/order
// to the former f1+f2 pair — block (b,u0) of f1 produced exactly the 16 T-rows
// that block (b,u0) of f2 consumed.
__global__ void fwd_kernel() {
    __shared__ float  Cs[16*128];
    __shared__ float  Ss[16*128];
    __shared__ float2 Ts[16*128];
    int b  = blockIdx.x;
    int u0 = blockIdx.y << 4;
    int tid = threadIdx.x;
    for (int i = tid; i < 2048; i += 256) {
        int lu = i >> 7, h = i & 127;
        Cs[i] = g_Cf[((u0 + lu) << 7) + h];
        Ss[i] = g_Sf[((u0 + lu) << 7) + h];
    }
    __syncthreads();
    // phase A: h-transform, 8 u-values per thread, write to smem Ts
    {
        int w = tid & 127, half = tid >> 7;
        const float* x = g_out + (((b << 6) + 32) << 14);
        float ar[8], ai[8];
#pragma unroll
        for (int j = 0; j < 8; j++) { ar[j] = 0.f; ai[j] = 0.f; }
        for (int h = 0; h < 128; h++) {
            float xv = x[(h << 7) + w];
#pragma unroll
            for (int j = 0; j < 8; j++) {
                int lu = (half << 3) + j;
                ar[j] += xv * Cs[(lu << 7) + h];
                ai[j] -= xv * Ss[(lu << 7) + h];
            }
        }
#pragma unroll
        for (int j = 0; j < 8; j++) {
            int lu = (half << 3) + j;
            Ts[(lu << 7) + w] = make_float2(ar[j], ai[j]);
        }
    }
    __syncthreads();
    // phase B: w-transform of the 16 rows, scale 1/128, write X
    {
        int v = tid & 127, half = tid >> 7;
        float ar[8], ai[8];
#pragma unroll
        for (int j = 0; j < 8; j++) { ar[j] = 0.f; ai[j] = 0.f; }
        const float* Cp = g_Cf + (v << 7);
        const float* Sp = g_Sf + (v << 7);
        for (int w = 0; w < 128; w++) {
            float c = Cp[w], s = Sp[w];
#pragma unroll
            for (int j = 0; j < 8; j++) {
                float2 t = Ts[(((half << 3) + j) << 7) + w];
                ar[j] += t.x * c + t.y * s;
                ai[j] += t.y * c - t.x * s;
            }
        }
#pragma unroll
        for (int j = 0; j < 8; j++) {
            int u = u0 + (half << 3) + j;
            g_X[(((b << 7) + u) << 7) + v] = make_float2(ar[j] * (1.f/128.f),
                                                         ai[j] * (1.f/128.f));
        }
    }
}

// ---------------- weight reduce (537MB read) --------------------------------
__global__ void wred_kernel(const float* __restrict__ wrp,
                            const float* __restrict__ wip) {
    int t = blockIdx.x * blockDim.x + threadIdx.x;   // 0..262143
    int cin = t >> 12;
    int q4  = t & 4095;
    const float4* R = (const float4*)wrp;
    const float4* I = (const float4*)wip;
    float4 sr = make_float4(0.f,0.f,0.f,0.f);
    float4 si = make_float4(0.f,0.f,0.f,0.f);
#pragma unroll 16
    for (int o = 0; o < 64; o++) {
        float4 a = __ldg(&R[(((cin << 6) + o) << 12) + q4]);
        float4 b = __ldg(&I[(((cin << 6) + o) << 12) + q4]);
        sr.x += a.x; sr.y += a.y; sr.z += a.z; sr.w += a.w;
        si.x += b.x; si.y += b.y; si.z += b.z; si.w += b.w;
    }
    float4* W4 = (float4*)g_W;
    W4[(cin << 13) + (q4 << 1) + 0] = make_float4(sr.x, si.x, sr.y, si.y);
    W4[(cin << 13) + (q4 << 1) + 1] = make_float4(sr.z, si.z, sr.w, si.w);
}

// ---------------- fused inverse: (X*W) -> ifft2 -> out1 ---------------------
// One block per image (b*64+cin). Whole 128x128 complex image in smem
// (row stride 130 float2 to avoid bank conflicts in the column stages).
#define RS_ 130
__global__ void inv_kernel() {
    extern __shared__ float2 sD[];               // 128*130 float2
    __shared__ float2 E16s[256];
    __shared__ float2 E8s[64];
    __shared__ float2 TWs[128];
    __shared__ float2 wb[8][128];
    int tid = threadIdx.x;
    int img = blockIdx.x;
    int b = img >> 6, cin = img & 63;
    if (tid < 256) E16s[tid] = g_E16[tid];
    if (tid < 64)  E8s[tid]  = g_E8[tid];
    if (tid < 128) TWs[tid]  = g_TW[tid];
    // load + multiply: sD[u][v] = X[b,u,v] * W[cin,u,v]
    const float2* X = g_X + (b << 14);
    const float2* W = g_W + (cin << 14);
    for (int i = tid; i < 16384; i += 256) {
        int u = i >> 7, v = i & 127;
        sD[u*RS_ + v] = cmul(X[i], W[i]);
    }
    __syncthreads();
    // stage1 (columns): G[u1*16+h2][v] = TW[h2,u1] * sum_u2 E16[h2,u2]*D[u1+8u2][v]
    for (int pass = 0; pass < 4; pass++) {
        int v  = (pass << 5) + (tid >> 3);
        int u1 = tid & 7;
        float2 y[16];
#pragma unroll
        for (int u2 = 0; u2 < 16; u2++) y[u2] = sD[(u1 + (u2 << 3))*RS_ + v];
        float2 o[16];
#pragma unroll
        for (int h2 = 0; h2 < 16; h2++) {
            float2 acc = make_float2(0.f, 0.f);
#pragma unroll
            for (int u2 = 0; u2 < 16; u2++) {
                float2 e = E16s[(h2 << 4) + u2];
                acc.x += e.x * y[u2].x - e.y * y[u2].y;
                acc.y += e.x * y[u2].y + e.y * y[u2].x;
            }
            o[h2] = cmul(TWs[(h2 << 3) + u1], acc);
        }
        __syncthreads();
#pragma unroll
        for (int h2 = 0; h2 < 16; h2++) sD[((u1 << 4) + h2)*RS_ + v] = o[h2];
        __syncthreads();
    }
    // stage2 (columns): T2[h2+16h1][v] = sum_u1 E8[h1,u1]*G[u1*16+h2][v]
    for (int q = 0; q < 8; q++) {
        int idx = (q << 8) + tid;
        int v = idx & 127, h2 = idx >> 7;
        float2 g[8];
#pragma unroll
        for (int u1 = 0; u1 < 8; u1++) g[u1] = sD[((u1 << 4) + h2)*RS_ + v];
        float2 o[8];
#pragma unroll
        for (int h1 = 0; h1 < 8; h1++) {
            float2 acc = make_float2(0.f, 0.f);
#pragma unroll
            for (int u1 = 0; u1 < 8; u1++) {
                float2 e = E8s[(h1 << 3) + u1];
                acc.x += e.x * g[u1].x - e.y * g[u1].y;
                acc.y += e.x * g[u1].y + e.y * g[u1].x;
            }
            o[h1] = acc;
        }
        __syncthreads();
#pragma unroll
        for (int h1 = 0; h1 < 8; h1++) sD[(h2 + (h1 << 4))*RS_ + v] = o[h1];
        __syncthreads();
    }
    // stage3+4 (rows), warp-per-row with per-warp staging buffer
    int wid = tid >> 5, ln = tid & 31;
    float* out1 = g_out1 + (img << 14);
    for (int r = wid; r < 128; r += 8) {
        float2 h4[4];
#pragma unroll
        for (int j = 0; j < 4; j++) {
            int idx = ln + (j << 5);
            int v1 = idx >> 4, w2 = idx & 15;
            float2 acc = make_float2(0.f, 0.f);
#pragma unroll
            for (int v2 = 0; v2 < 16; v2++) {
                float2 e = E16s[(w2 << 4) + v2];
                float2 t = sD[r*RS_ + v1 + (v2 << 3)];
                acc.x += e.x * t.x - e.y * t.y;
                acc.y += e.x * t.y + e.y * t.x;
            }
            h4[j] = cmul(TWs[(w2 << 3) + v1], acc);
        }
#pragma unroll
        for (int j = 0; j < 4; j++) wb[wid][ln + (j << 5)] = h4[j];
        __syncwarp();
#pragma unroll
        for (int j = 0; j < 4; j++) {
            int w = ln + (j << 5);
            int w2 = w & 15, w1 = w >> 4;
            float rr = 0.f;
#pragma unroll
            for (int v1 = 0; v1 < 8; v1++) {
                float2 e = E8s[(w1 << 3) + v1];
                float2 hh = wb[wid][(v1 << 4) + w2];
                rr += e.x * hh.x - e.y * hh.y;
            }
            out1[(r << 7) + w] = rr * (1.f/128.f);
        }
        __syncwarp();
    }
}

// ---------------- fold conv chain into one matrix + bias --------------------
__global__ void combine_kernel(const float* __restrict__ w0w,
                               const float* __restrict__ w0b,
                               const float* __restrict__ cvw,
                               const float* __restrict__ cvb,
                               const float* __restrict__ cv1w,
                               const float* __restrict__ cv1b) {
    __shared__ float sA[4096];
    __shared__ float sb1[64];
    int tid = threadIdx.x;
    for (int i = tid; i < 4096; i += 256) {
        int o = i >> 6, c = i & 63;
        float s = 0.f;
        for (int k = 0; k < 64; k++) s += w0w[(o << 6) + k] * cvw[(k << 6) + c];
        sA[i] = s;
    }
    if (tid < 64) {
        float s = 0.f;
        for (int k = 0; k < 64; k++) s += w0w[(tid << 6) + k] * cvb[k];
        sb1[tid] = s + w0b[tid];
    }
    __syncthreads();
    for (int i = tid; i < 4096; i += 256) {
        int o = i >> 6, c = i & 63;
        float s = 0.f;
        for (int k = 0; k < 64; k++) s += cv1w[(o << 6) + k] * sA[(k << 6) + c];
        g_Mt[(c << 6) + o] = s;   // transposed store
    }
    if (tid < 64) {
        float s = 0.f;
        for (int k = 0; k < 64; k++) s += cv1w[(tid << 6) + k] * sb1[k];
        g_bias2[tid] = s + cv1b[tid];
    }
}

// ---------------- fused out2 + mix + squared-error (split o-halves) ---------
__global__ void final_kernel(const float* __restrict__ ft,
                             const float* __restrict__ rate1,
                             const float* __restrict__ rate2) {
    __shared__ float Mt[C_*32];
    __shared__ float bsh[32];
    __shared__ float red[256];
    int tid = threadIdx.x;
    int half = blockIdx.y;
    for (int i = tid; i < C_*32; i += 256) {
        int cin = i >> 5, o = i & 31;
        Mt[i] = g_Mt[(cin << 6) + (half << 5) + o];
    }
    if (tid < 32) bsh[tid] = g_bias2[(half << 5) + tid];
    __syncthreads();
    int p = blockIdx.x * 256 + tid;   // pixel
    int b = p >> 14, sp = p & 16383;
    int base = (b << 6) << 14;
    float acc2[32];
#pragma unroll
    for (int o = 0; o < 32; o++) acc2[o] = 0.f;
    const float4* Mt4 = (const float4*)Mt;
    for (int cin = 0; cin < 64; cin++) {
        float x = g_out[base + (cin << 14) + sp];
#pragma unroll
        for (int o4 = 0; o4 < 8; o4++) {
            float4 w4 = Mt4[(cin << 3) + o4];
            acc2[o4*4+0] += x * w4.x;
            acc2[o4*4+1] += x * w4.y;
            acc2[o4*4+2] += x * w4.z;
            acc2[o4*4+3] += x * w4.w;
        }
    }
    float r1 = rate1[0], r2 = rate2[0];
    float ssum = 0.f;
    const float4* ftp = (const float4*)(ft + ((size_t)p << 6) + (half << 5));
#pragma unroll
    for (int c4 = 0; c4 < 8; c4++) {
        float4 f = __ldg(&ftp[c4]);
        float fv[4] = { f.x, f.y, f.z, f.w };
#pragma unroll
        for (int j = 0; j < 4; j++) {
            int c = c4*4 + j;
            float o1 = g_out1[base + (((half << 5) + c) << 14) + sp];
            float mk = r1 * o1 + r2 * (acc2[c] + bsh[c]);
            float d = mk - fv[j];
            ssum += d * d;
        }
    }
    red[tid] = ssum;
    __syncthreads();
    for (int s = 128; s > 0; s >>= 1) {
        if (tid < s) red[tid] += red[tid + s];
        __syncthreads();
    }
    if (tid == 0) g_part[blockIdx.y * 128 + blockIdx.x] = red[0];
}

__global__ void reduce2_kernel(float* __restrict__ out) {
    __shared__ double red[256];
    int tid = threadIdx.x;
    red[tid] = (double)g_part[tid];
    __syncthreads();
    for (int s = 128; s > 0; s >>= 1) {
        if (tid < s) red[tid] += red[tid + s];
        __syncthreads();
    }
    if (tid == 0) out[0] = (float)(red[0] / 2097152.0);
}

// ---------------- launch ----------------------------------------------------
extern "C" void kernel_launch(void* const* d_in, const int* in_sizes, int n_in,
                              void* d_out, int out_size) {
    const float* fs    = (const float*)d_in[0];
    const float* ft    = (const float*)d_in[1];
    const float* wq    = (const float*)d_in[2];
    const float* wk    = (const float*)d_in[3];
    const float* wv    = (const float*)d_in[4];
    const float* relh  = (const float*)d_in[5];
    const float* relw  = (const float*)d_in[6];
    const float* w1r   = (const float*)d_in[7];
    const float* w1i   = (const float*)d_in[8];
    const float* w0w   = (const float*)d_in[9];
    const float* w0b   = (const float*)d_in[10];
    const float* cvw   = (const float*)d_in[11];
    const float* cvb   = (const float*)d_in[12];
    const float* cv1w  = (const float*)d_in[13];
    const float* cv1b  = (const float*)d_in[14];
    const float* rate1 = (const float*)d_in[15];
    const float* rate2 = (const float*)d_in[16];
    float* out = (float*)d_out;

    // idempotent, deterministic, not a stream op — safe on every call
    cudaFuncSetAttribute(inv_kernel,
                         cudaFuncAttributeMaxDynamicSharedMemorySize,
                         128 * RS_ * (int)sizeof(float2));

    init_tables_kernel<<<64, 256>>>();
    qkv_kernel<<<dim3(128, 6), 256>>>(fs, wq, wk, wv);
    att_kernel<<<dim3(64, 128), 256>>>(relh, relw);
    fwd_kernel<<<dim3(2, 8), 256>>>();
    wred_kernel<<<1024, 256>>>(w1r, w1i);
    inv_kernel<<<128, 256, 128 * RS_ * (int)sizeof(float2)>>>();
    combine_kernel<<<1, 256>>>(w0w, w0b, cvw, cvb, cv1w, cv1b);
    final_kernel<<<dim3(128, 2), 256>>>(ft, rate1, rate2);
    reduce2_kernel<<<1, 256>>>(out);
}